// round 16
// baseline (speedup 1.0000x reference)
#include <cuda_runtime.h>
#include <cuda_fp16.h>
#include <cstdint>

// Problem constants
#define NQ      16384      // B*H*W
#define NEG     4096       // embeddings per group
#define GR      4
#define KD      64         // embedding dim
#define TQH     64         // queries per CTA (half tile)
#define NT      128        // e per tile
#define NTILES  32         // tiles per group
#define CAP     64         // candidate capacity per row

#define QUANT_SZ 4194304ULL
#define ME_OFFC  4194317ULL   // QUANT_SZ + 13 (odd -> unaligned head)
#define IDX_OFFC 71303181ULL  // ME_OFFC + 16384*4096

typedef unsigned long long ull;

// ---- device scratch (static, no allocation) ----
__device__ int      g_idx[NQ * GR];               // final argmax indices
__device__ float    g_embn[NEG * GR * KD];        // normalized embedding (fp32)
__device__ int      g_embh[GR * NTILES * 4096];   // fp16 swizzled 16KB tile images
__device__ int      g_hist[NEG];                  // histogram of idx[:, 3]
__device__ int      g_done;                       // scatter block arrival count

// ============================================================================
// PTX helpers (base-target: ldmatrix sm_75+, mma.sync sm_80+)
// ============================================================================
__device__ __forceinline__ uint32_t smem_u32(const void* p) {
    uint32_t a;
    asm("{ .reg .u64 t; cvta.to.shared.u64 t, %1; cvt.u32.u64 %0, t; }"
        : "=r"(a) : "l"(p));
    return a;
}
#define LDSM_X4(r, addr) \
    asm volatile("ldmatrix.sync.aligned.m8n8.x4.shared.b16 {%0,%1,%2,%3}, [%4];" \
        : "=r"((r)[0]), "=r"((r)[1]), "=r"((r)[2]), "=r"((r)[3]) : "r"(addr))

__device__ __forceinline__ void mma16816(float* c, const uint32_t* a,
                                         const uint32_t* b) {
    asm volatile("mma.sync.aligned.m16n8k16.row.col.f32.f16.f16.f32 "
        "{%0,%1,%2,%3}, {%4,%5,%6,%7}, {%8,%9}, {%0,%1,%2,%3};"
        : "+f"(c[0]), "+f"(c[1]), "+f"(c[2]), "+f"(c[3])
        : "r"(a[0]), "r"(a[1]), "r"(a[2]), "r"(a[3]), "r"(b[0]), "r"(b[1]));
}

// ============================================================================
// emb prep (+ hist/losses/done init folded): normalize rows -> g_embn(fp32);
// fp16 XOR-swizzled tile images -> g_embh.  One warp per embedding row.
// ============================================================================
__global__ void embprep_kernel(const float* __restrict__ emb,
                               float* __restrict__ out)
{
    int gidx = blockIdx.x * blockDim.x + threadIdx.x;
    if (gidx < NEG) g_hist[gidx] = 0;
    if (gidx < 13)  out[QUANT_SZ + gidx] = 0.0f;   // losses + perp slot
    if (gidx == 13) g_done = 0;

    int warp = gidx >> 5;
    int lane = threadIdx.x & 31;
    float2 v = reinterpret_cast<const float2*>(emb + (size_t)warp * KD)[lane];
    float s = v.x * v.x + v.y * v.y;
    #pragma unroll
    for (int m = 16; m >= 1; m >>= 1) s += __shfl_xor_sync(0xffffffffu, s, m);
    float inv = 1.0f / fmaxf(sqrtf(s), 1e-12f);
    float2 o = make_float2(v.x * inv, v.y * inv);
    reinterpret_cast<float2*>(g_embn + (size_t)warp * KD)[lane] = o;

    __half2 h2 = __floats2half2_rn(o.x, o.y);
    int w; memcpy(&w, &h2, 4);
    int g  = warp >> 12;
    int el = warp & 4095;
    int et = el >> 7, er = el & 127;
    int ui = er * 32 + ((((lane >> 2)) ^ (er & 7)) << 2) + (lane & 3);
    g_embh[(size_t)(g * NTILES + et) * 4096 + ui] = w;
}

// ============================================================================
// Fused GEMM + argmax + rescore + quant, HALF-TILE items.  One CTA per
// (64-query half, group): grid 1024, 256 threads, 2 CTAs/SM.
// M=64 HMMA core (warp = 32q x 32e, acc[2][4][4]); smem candidates; exact
// fp32 rescore tail; quant slice write; 65536-float ME zero slice.
// Smem: smarg[64]@0 | sn2[256]@256 | scnt@1280 | swin@1536 | A 8KB@2048 |
//   B0@10240 B1@26624 (16KB each; zsh reuses B0) | scand 16KB@43008.
//   Total 59392.
// ============================================================================
__global__ __launch_bounds__(256, 2)
void vq_fused_kernel(const float* __restrict__ z, float* __restrict__ out)
{
    extern __shared__ __align__(1024) char smem[];
    float* smarg = reinterpret_cast<float*>(smem);            // 64 floats
    float* sn2   = reinterpret_cast<float*>(smem + 256);      // 256 floats
    int*   scnt  = reinterpret_cast<int*>(smem + 1280);       // 64 ints
    int*   swin  = reinterpret_cast<int*>(smem + 1536);       // 64 ints
    int*   scand = reinterpret_cast<int*>(smem + 43008);      // 64*CAP ints
    uint32_t sbase = smem_u32(smem);
    const uint32_t aA = sbase + 2048;
    const uint32_t aBh[2] = { sbase + 10240, sbase + 26624 };
    int4* sBh4[2] = { reinterpret_cast<int4*>(smem + 10240),
                      reinterpret_cast<int4*>(smem + 26624) };
    float* zsh = reinterpret_cast<float*>(smem + 10240);      // 16KB after loop

    const int tid   = threadIdx.x;
    const int item  = blockIdx.x;
    const int g     = item & 3;
    const int qbase = (item >> 2) * TQH;
    const int b     = qbase >> 10;
    const int hwb   = qbase & 1023;
    const float* zb = z + (size_t)b * 262144 + (size_t)(g * 64) * 1024 + hwb;

    // min_encodings zero-slice for this CTA: 65536 floats
    const size_t S = ME_OFFC + (size_t)item * 65536;
    float4* me4 = reinterpret_cast<float4*>(out + S + 3);   // 16B aligned

    // ---- prologue: build A tile (64q x 64c fp16, swizzled) + margins ----
    {
        const int q  = tid & 63;
        const int ph = tid >> 6;                 // 0..3, c-pairs ph*8..+7
        __half2* A2 = reinterpret_cast<__half2*>(smem + 2048);
        float n2 = 0.0f;
        #pragma unroll
        for (int i = 0; i < 8; i++) {
            int c = (ph * 8 + i) * 2;
            float v0 = zb[(size_t)c * 1024 + q];
            float v1 = zb[(size_t)(c + 1) * 1024 + q];
            n2 += v0 * v0 + v1 * v1;
            int ui = q * 32 + (((c >> 3) ^ (q & 7)) << 2) + ((c & 7) >> 1);
            A2[ui] = __floats2half2_rn(v0, v1);
        }
        sn2[q * 4 + ph] = n2;
        if (tid < 64) scnt[tid] = 0;
        // preload B(0): 16KB = 1024 int4, 4 per thread
        {
            const int4* s4 = reinterpret_cast<const int4*>(
                g_embh + (size_t)(g * NTILES) * 4096);
            #pragma unroll
            for (int i = 0; i < 4; i++) sBh4[0][tid + i * 256] = s4[tid + i * 256];
        }
        __syncthreads();
        if (tid < 64)
            smarg[tid] = 0.006f * sqrtf(sn2[tid * 4] + sn2[tid * 4 + 1] +
                                        sn2[tid * 4 + 2] + sn2[tid * 4 + 3]);
        __syncthreads();
    }

    const int w  = tid >> 5;
    const int l  = tid & 31;
    const int qw = (w & 1) * 32;      // 2 q-strips of 32
    const int ew = (w >> 1) * 32;     // 4 e-chunks of 32

    float rm[4], marg[4];
    int   rloc[4];
    #pragma unroll
    for (int qb = 0; qb < 2; qb++)
        #pragma unroll
        for (int h = 0; h < 2; h++) {
            int slot = qb * 2 + h;
            int rq = qw + qb * 16 + (l >> 2) + h * 8;
            rm[slot]   = -3.0e38f;
            marg[slot] = smarg[rq];
            rloc[slot] = rq;
        }

    const int4* esrc = reinterpret_cast<const int4*>(
        g_embh + (size_t)(g * NTILES) * 4096);

    if (tid < 3)  out[S + tid] = 0.0f;        // ME unaligned head
    if (tid == 3) out[S + 65535] = 0.0f;      // ME tail float

    for (int t = 0; t < NTILES; t++) {
        // prefetch next B tile into the other buffer
        if (t + 1 < NTILES) {
            const int4* s4 = esrc + (size_t)(t + 1) * 1024;
            int4* d4 = sBh4[(t + 1) & 1];
            #pragma unroll
            for (int i = 0; i < 4; i++) d4[tid + i * 256] = s4[tid + i * 256];
        }
        // streamed zero-stores for min_encodings slice (512 float4/tile)
        {
            const float4 z4 = make_float4(0.f, 0.f, 0.f, 0.f);
            #pragma unroll
            for (int i = 0; i < 2; i++) {
                int j = t * 512 + i * 256 + tid;
                if (j < 16383) me4[j] = z4;
            }
        }

        float acc[2][4][4];
        #pragma unroll
        for (int qb = 0; qb < 2; qb++)
            #pragma unroll
            for (int eb = 0; eb < 4; eb++)
                #pragma unroll
                for (int j = 0; j < 4; j++) acc[qb][eb][j] = 0.0f;

        const uint32_t base = aBh[t & 1];
        #pragma unroll
        for (int ks = 0; ks < 4; ks++) {
            uint32_t RA[2][4];
            #pragma unroll
            for (int qb = 0; qb < 2; qb++) {
                int row = qw + qb * 16 + (l & 15);
                int blk = ks * 2 + (l >> 4);
                LDSM_X4(RA[qb], aA + row * 128 + ((blk ^ (row & 7)) << 4));
            }
            uint32_t RB[2][4];
            #pragma unroll
            for (int ebp = 0; ebp < 2; ebp++) {
                int row = ew + ebp * 16 + (l & 7) + ((l >> 4) << 3);
                int blk = ks * 2 + ((l >> 3) & 1);
                LDSM_X4(RB[ebp], base + row * 128 + ((blk ^ (row & 7)) << 4));
            }
            #pragma unroll
            for (int qb = 0; qb < 2; qb++)
                #pragma unroll
                for (int eb = 0; eb < 4; eb++)
                    mma16816(acc[qb][eb], RA[qb], &RB[eb >> 1][(eb & 1) * 2]);
        }

        // ---- epilogue: half2 max tree + gated scan, smem candidate push ----
        #pragma unroll
        for (int qb = 0; qb < 2; qb++)
            #pragma unroll
            for (int h = 0; h < 2; h++) {
                const int slot = qb * 2 + h;
                __half2 m2 = __floats2half2_rn(acc[qb][0][h * 2],
                                               acc[qb][0][h * 2 + 1]);
                #pragma unroll
                for (int eb = 1; eb < 4; eb++)
                    m2 = __hmax2(m2, __floats2half2_rn(acc[qb][eb][h * 2],
                                                       acc[qb][eb][h * 2 + 1]));
                float mx = __half2float(__hmax(__low2half(m2), __high2half(m2)));
                mx = fmaxf(mx, __shfl_xor_sync(0xffffffffu, mx, 1));
                mx = fmaxf(mx, __shfl_xor_sync(0xffffffffu, mx, 2));
                if (mx > rm[slot]) rm[slot] = mx;
                const float thr = rm[slot] - marg[slot];
                if (__any_sync(0xffffffffu, mx >= thr - 0.015f)) {
                    #pragma unroll
                    for (int eb = 0; eb < 4; eb++)
                        #pragma unroll
                        for (int j = 0; j < 2; j++) {
                            float vv = acc[qb][eb][h * 2 + j];
                            if (vv >= thr) {
                                int sc = atomicAdd(&scnt[rloc[slot]], 1);
                                if (sc < CAP)
                                    scand[rloc[slot] * CAP + sc] =
                                        t * NT + ew + eb * 8 + (l & 3) * 2 + j;
                            }
                        }
                }
            }
        __syncthreads();
    }

    // ======================= fused rescore tail =======================
    // reload fp32 z rows into the (now dead) B0 buffer: zsh[c*64+q]
    #pragma unroll
    for (int i = 0; i < 16; i++) {
        int idx = tid + i * 256;       // 4096 = 64c * 64q
        int c = idx >> 6, q2 = idx & 63;
        zsh[c * 64 + q2] = zb[(size_t)c * 1024 + q2];
    }
    __syncthreads();

    // warp w rescores rows w*8 .. w*8+7 (exact fp32, first-index ties)
    const float* embg = g_embn + (size_t)g * NEG * KD;
    for (int r8 = 0; r8 < 8; r8++) {
        const int rq = w * 8 + r8;
        const int cnt = scnt[rq];
        float bv = -3.0e38f;
        int   be = 0x7FFFFFFF;
        if (cnt > CAP) {
            for (int e = l; e < NEG; e += 32) {
                const float4* er = reinterpret_cast<const float4*>(
                    embg + (size_t)e * KD);
                float acc = 0.0f;
                #pragma unroll
                for (int kk = 0; kk < 16; kk++) {
                    float4 ev = er[kk];
                    acc = fmaf(zsh[(kk * 4 + 0) * 64 + rq], ev.x, acc);
                    acc = fmaf(zsh[(kk * 4 + 1) * 64 + rq], ev.y, acc);
                    acc = fmaf(zsh[(kk * 4 + 2) * 64 + rq], ev.z, acc);
                    acc = fmaf(zsh[(kk * 4 + 3) * 64 + rq], ev.w, acc);
                }
                if (acc > bv || (acc == bv && e < be)) { bv = acc; be = e; }
            }
        } else {
            for (int cbase = 0; cbase < cnt; cbase += 32) {
                int c = cbase + l;
                if (c < cnt) {
                    int e = scand[rq * CAP + c];
                    const float4* er = reinterpret_cast<const float4*>(
                        embg + (size_t)e * KD);
                    float acc = 0.0f;
                    #pragma unroll
                    for (int kk = 0; kk < 16; kk++) {
                        float4 ev = er[kk];
                        acc = fmaf(zsh[(kk * 4 + 0) * 64 + rq], ev.x, acc);
                        acc = fmaf(zsh[(kk * 4 + 1) * 64 + rq], ev.y, acc);
                        acc = fmaf(zsh[(kk * 4 + 2) * 64 + rq], ev.z, acc);
                        acc = fmaf(zsh[(kk * 4 + 3) * 64 + rq], ev.w, acc);
                    }
                    if (acc > bv || (acc == bv && e < be)) { bv = acc; be = e; }
                }
            }
        }
        unsigned u = __float_as_uint(bv);
        u = ((int)u < 0) ? ~u : (u | 0x80000000u);
        unsigned m = __reduce_max_sync(0xffffffffu, u);
        unsigned bidm = (u == m) ? (unsigned)be : 0xFFFFFFFFu;
        unsigned bi = __reduce_min_sync(0xffffffffu, bidm);
        if (l == 0) {
            swin[rq] = (int)bi;
            int n = qbase + rq;
            g_idx[n * GR + g] = (int)bi;
            out[IDX_OFFC + (size_t)n * GR + g] = (float)bi;
        }
    }
    __syncthreads();

    // ======================= fused quant tail =======================
    // out[b, g*64+c, hwb+q] = embn[g*4096 + swin[q], c]; coalesced stores.
    {
        const int q  = tid & 63;
        const int ph = tid >> 6;                 // c = ph*16 .. +15
        const float* er = embg + (size_t)swin[q] * KD;
        float* oq = out + (size_t)b * 262144 + (size_t)(g * 64) * 1024 + hwb + q;
        #pragma unroll
        for (int i = 0; i < 16; i++) {
            int c = ph * 16 + i;
            oq[(size_t)c * 1024] = er[c];
        }
    }
}

// ============================================================================
// Scatter one-hot + histogram; the LAST block also reduces the histogram
// into perplexity (last-block pattern: threadfence + arrival counter).
// ============================================================================
__global__ void scatter_perp_kernel(float* __restrict__ out_me,
                                    float* __restrict__ out_p)
{
    __shared__ float red[32];
    __shared__ int   isLast;

    int tid = threadIdx.x;
    int n = blockIdx.x * blockDim.x + tid;
    if (n < NQ) {
        int v = g_idx[n * GR + 3];
        out_me[(size_t)n * NEG + v] = 1.0f;
        atomicAdd(&g_hist[v], 1);
    }

    __threadfence();
    __syncthreads();
    if (tid == 0) {
        int c = atomicAdd(&g_done, 1);
        isLast = (c == (int)gridDim.x - 1);
    }
    __syncthreads();

    if (isLast) {
        float s = 0.0f;
        for (int i = tid; i < NEG; i += blockDim.x) {
            float p = (float)g_hist[i] * (1.0f / 16384.0f);
            s += p * logf(p + 1e-10f);
        }
        #pragma unroll
        for (int m = 16; m >= 1; m >>= 1) s += __shfl_xor_sync(0xffffffffu, s, m);
        if ((tid & 31) == 0) red[tid >> 5] = s;
        __syncthreads();
        if (tid < 32) {
            float x = (tid < (int)(blockDim.x >> 5)) ? red[tid] : 0.0f;
            #pragma unroll
            for (int m = 16; m >= 1; m >>= 1)
                x += __shfl_xor_sync(0xffffffffu, x, m);
            if (tid == 0) out_p[0] = expf(-x);
        }
    }
}

// ============================================================================
// Output layout (fp32, concatenated, 71,368,717 elements):
//   [0, 4194304)            quant          (written in vq_fused_kernel)
//   [4194304, +12)          losses = zeros (written in embprep_kernel)
//   [4194316]               perplexity     (scatter_perp_kernel)
//   [4194317, +16384*4096)  min_encodings  (zeroed in vq_fused_kernel,
//                                           one-hot in scatter_perp_kernel)
//   [71303181, +65536)      idx            (written in vq_fused_kernel)
// ============================================================================
extern "C" void kernel_launch(void* const* d_in, const int* in_sizes, int n_in,
                              void* d_out, int out_size)
{
    const float* z   = (const float*)d_in[0];
    const float* emb = (const float*)d_in[1];
    float* out = (float*)d_out;

    const int SMEM = 59392;
    cudaFuncSetAttribute(vq_fused_kernel,
                         cudaFuncAttributeMaxDynamicSharedMemorySize, SMEM);

    embprep_kernel<<<2048, 256>>>(emb, out);

    vq_fused_kernel<<<1024, 256, SMEM>>>(z, out);

    scatter_perp_kernel<<<64, 256>>>(out + ME_OFFC, out + QUANT_SZ + 12);
}

// round 17
// speedup vs baseline: 1.4123x; 1.4123x over previous
#include <cuda_runtime.h>
#include <cuda_fp16.h>
#include <cstdint>

// Problem constants
#define NQ      16384      // B*H*W
#define NEG     4096       // embeddings per group
#define GR      4
#define KD      64         // embedding dim
#define TQ      128        // queries per block
#define NT      128        // e per tile
#define NTILES  32         // tiles per group
#define CAP     64         // candidate capacity per row

#define QUANT_SZ 4194304ULL
#define ME_OFFC  4194317ULL   // QUANT_SZ + 13 (odd -> unaligned head)
#define IDX_OFFC 71303181ULL  // ME_OFFC + 16384*4096

typedef unsigned long long ull;

// ---- device scratch (static, no allocation) ----
__device__ int      g_idx[NQ * GR];               // final argmax indices
__device__ float    g_embn[NEG * GR * KD];        // normalized embedding (fp32)
__device__ int      g_embh[GR * NTILES * 4096];   // fp16 swizzled 16KB tile images
__device__ int      g_hist[NEG];                  // histogram of idx[:, 3]
__device__ int      g_done;                       // scatter block arrival count

// ============================================================================
// PTX helpers (base-target: ldmatrix sm_75+, mma.sync sm_80+)
// ============================================================================
__device__ __forceinline__ uint32_t smem_u32(const void* p) {
    uint32_t a;
    asm("{ .reg .u64 t; cvta.to.shared.u64 t, %1; cvt.u32.u64 %0, t; }"
        : "=r"(a) : "l"(p));
    return a;
}
#define LDSM_X4(r, addr) \
    asm volatile("ldmatrix.sync.aligned.m8n8.x4.shared.b16 {%0,%1,%2,%3}, [%4];" \
        : "=r"((r)[0]), "=r"((r)[1]), "=r"((r)[2]), "=r"((r)[3]) : "r"(addr))

__device__ __forceinline__ void mma16816(float* c, const uint32_t* a,
                                         const uint32_t* b) {
    asm volatile("mma.sync.aligned.m16n8k16.row.col.f32.f16.f16.f32 "
        "{%0,%1,%2,%3}, {%4,%5,%6,%7}, {%8,%9}, {%0,%1,%2,%3};"
        : "+f"(c[0]), "+f"(c[1]), "+f"(c[2]), "+f"(c[3])
        : "r"(a[0]), "r"(a[1]), "r"(a[2]), "r"(a[3]), "r"(b[0]), "r"(b[1]));
}

// fp32 bits -> monotone sortable u32 key (order-preserving, exact)
__device__ __forceinline__ unsigned fkey(float v) {
    unsigned u = __float_as_uint(v);
    return ((int)u < 0) ? ~u : (u | 0x80000000u);
}

// ============================================================================
// emb prep (+ hist/losses/done init folded): normalize rows -> g_embn(fp32);
// fp16 XOR-swizzled tile images -> g_embh.  One warp per embedding row.
// ============================================================================
__global__ void embprep_kernel(const float* __restrict__ emb,
                               float* __restrict__ out)
{
    int gidx = blockIdx.x * blockDim.x + threadIdx.x;
    if (gidx < NEG) g_hist[gidx] = 0;
    if (gidx < 13)  out[QUANT_SZ + gidx] = 0.0f;   // losses + perp slot
    if (gidx == 13) g_done = 0;

    int warp = gidx >> 5;
    int lane = threadIdx.x & 31;
    float2 v = reinterpret_cast<const float2*>(emb + (size_t)warp * KD)[lane];
    float s = v.x * v.x + v.y * v.y;
    #pragma unroll
    for (int m = 16; m >= 1; m >>= 1) s += __shfl_xor_sync(0xffffffffu, s, m);
    float inv = 1.0f / fmaxf(sqrtf(s), 1e-12f);
    float2 o = make_float2(v.x * inv, v.y * inv);
    reinterpret_cast<float2*>(g_embn + (size_t)warp * KD)[lane] = o;

    __half2 h2 = __floats2half2_rn(o.x, o.y);
    int w; memcpy(&w, &h2, 4);
    int g  = warp >> 12;
    int el = warp & 4095;
    int et = el >> 7, er = el & 127;
    int ui = er * 32 + ((((lane >> 2)) ^ (er & 7)) << 2) + (lane & 3);
    g_embh[(size_t)(g * NTILES + et) * 4096 + ui] = w;
}

// ============================================================================
// Fused GEMM + argmax + rescore + quant (R13/R15 core).  One CTA per
// (qtile, group), grid 512, 256 threads, 2 CTAs/SM.  R8 HMMA core; smem
// candidates; exact fp32 rescore tail (2 rows/warp, half-warp each);
// quant slice write; balanced per-item ME zero-stores.
// Smem: smarg[128]@0 | scnt@576 | swin@1088 | A 16KB@2048 |
//   Bh0@18432 Bh1@34816 (zsh reuses Bh after loop) | scand 32KB@51200.
//   Total 83968.
// ============================================================================
__global__ __launch_bounds__(256, 2)
void vq_fused_kernel(const float* __restrict__ z, float* __restrict__ out)
{
    extern __shared__ __align__(1024) char smem[];
    float* smarg = reinterpret_cast<float*>(smem);            // 128 floats
    int*   scnt  = reinterpret_cast<int*>(smem + 576);        // 128 ints
    int*   swin  = reinterpret_cast<int*>(smem + 1088);       // 128 ints
    int*   scand = reinterpret_cast<int*>(smem + 51200);      // 128*CAP ints
    uint32_t sbase = smem_u32(smem);
    const uint32_t aA = sbase + 2048;
    const uint32_t aBh[2] = { sbase + 18432, sbase + 34816 };
    int4* sBh4[2] = { reinterpret_cast<int4*>(smem + 18432),
                      reinterpret_cast<int4*>(smem + 34816) };
    float* zsh = reinterpret_cast<float*>(smem + 18432);      // 32KB after loop

    const int tid   = threadIdx.x;
    const int item  = blockIdx.x;
    const int g     = item & 3;
    const int qbase = (item >> 2) * TQ;
    const int b     = qbase >> 10;
    const int hwb   = qbase & 1023;
    const float* zb = z + (size_t)b * 262144 + (size_t)(g * 64) * 1024 + hwb;

    // min_encodings zero-slice for this CTA: 131072 floats
    const size_t S = ME_OFFC + (size_t)item * 131072;
    float4* me4 = reinterpret_cast<float4*>(out + S + 3);   // 16B aligned

    // ---- prologue: build A tile (fp16, swizzled) + per-row margin ----
    {
        const int q  = tid & 127;
        const int ph = tid >> 7;                 // c-pairs ph*16..+15
        __half2* A2 = reinterpret_cast<__half2*>(smem + 2048);
        float n2 = 0.0f;
        #pragma unroll
        for (int i = 0; i < 16; i++) {
            int c = (ph * 16 + i) * 2;
            float v0 = zb[(size_t)c * 1024 + q];
            float v1 = zb[(size_t)(c + 1) * 1024 + q];
            n2 += v0 * v0 + v1 * v1;
            int ui = q * 32 + (((c >> 3) ^ (q & 7)) << 2) + ((c & 7) >> 1);
            A2[ui] = __floats2half2_rn(v0, v1);
        }
        if (ph == 0) smarg[q] = n2;
        if (tid < 128) scnt[tid] = 0;
        // preload B(0)
        {
            const int4* s4 = reinterpret_cast<const int4*>(
                g_embh + (size_t)(g * NTILES) * 4096);
            #pragma unroll
            for (int i = 0; i < 4; i++) sBh4[0][tid + i * 256] = s4[tid + i * 256];
        }
        __syncthreads();
        if (ph == 1) smarg[q] = 0.006f * sqrtf(smarg[q] + n2);
        __syncthreads();
    }

    const int w  = tid >> 5;
    const int l  = tid & 31;
    const int qw = (w & 3) * 32;
    const int ew = (w >> 2) * 64;

    float rm[4], marg[4];
    int   rloc[4];
    #pragma unroll
    for (int qb = 0; qb < 2; qb++)
        #pragma unroll
        for (int h = 0; h < 2; h++) {
            int slot = qb * 2 + h;
            int rq = qw + qb * 16 + (l >> 2) + h * 8;
            rm[slot]   = -3.0e38f;
            marg[slot] = smarg[rq];
            rloc[slot] = rq;
        }

    const int4* esrc = reinterpret_cast<const int4*>(
        g_embh + (size_t)(g * NTILES) * 4096);

    if (tid < 3)  out[S + tid] = 0.0f;        // ME unaligned head
    if (tid == 3) out[S + 131071] = 0.0f;     // ME tail float

    for (int t = 0; t < NTILES; t++) {
        // prefetch next B tile into the other buffer
        if (t + 1 < NTILES) {
            const int4* s4 = esrc + (size_t)(t + 1) * 1024;
            int4* d4 = sBh4[(t + 1) & 1];
            #pragma unroll
            for (int i = 0; i < 4; i++) d4[tid + i * 256] = s4[tid + i * 256];
        }
        // streamed zero-stores for min_encodings slice
        {
            const float4 z4 = make_float4(0.f, 0.f, 0.f, 0.f);
            #pragma unroll
            for (int i = 0; i < 4; i++) {
                int j = t * 1024 + i * 256 + tid;
                if (j < 32767) me4[j] = z4;
            }
        }

        float acc[2][8][4];
        #pragma unroll
        for (int qb = 0; qb < 2; qb++)
            #pragma unroll
            for (int eb = 0; eb < 8; eb++)
                #pragma unroll
                for (int j = 0; j < 4; j++) acc[qb][eb][j] = 0.0f;

        const uint32_t base = aBh[t & 1];
        #pragma unroll
        for (int ks = 0; ks < 4; ks++) {
            uint32_t RA[2][4];
            #pragma unroll
            for (int qb = 0; qb < 2; qb++) {
                int row = qw + qb * 16 + (l & 15);
                int blk = ks * 2 + (l >> 4);
                LDSM_X4(RA[qb], aA + row * 128 + ((blk ^ (row & 7)) << 4));
            }
            uint32_t RB[4][4];
            #pragma unroll
            for (int ebp = 0; ebp < 4; ebp++) {
                int row = ew + ebp * 16 + (l & 7) + ((l >> 4) << 3);
                int blk = ks * 2 + ((l >> 3) & 1);
                LDSM_X4(RB[ebp], base + row * 128 + ((blk ^ (row & 7)) << 4));
            }
            #pragma unroll
            for (int qb = 0; qb < 2; qb++)
                #pragma unroll
                for (int eb = 0; eb < 8; eb++)
                    mma16816(acc[qb][eb], RA[qb], &RB[eb >> 1][(eb & 1) * 2]);
        }

        // ---- epilogue: half2 max tree + gated scan, smem candidate push ----
        #pragma unroll
        for (int qb = 0; qb < 2; qb++)
            #pragma unroll
            for (int h = 0; h < 2; h++) {
                const int slot = qb * 2 + h;
                __half2 m2 = __floats2half2_rn(acc[qb][0][h * 2],
                                               acc[qb][0][h * 2 + 1]);
                #pragma unroll
                for (int eb = 1; eb < 8; eb++)
                    m2 = __hmax2(m2, __floats2half2_rn(acc[qb][eb][h * 2],
                                                       acc[qb][eb][h * 2 + 1]));
                float mx = __half2float(__hmax(__low2half(m2), __high2half(m2)));
                mx = fmaxf(mx, __shfl_xor_sync(0xffffffffu, mx, 1));
                mx = fmaxf(mx, __shfl_xor_sync(0xffffffffu, mx, 2));
                if (mx > rm[slot]) rm[slot] = mx;
                const float thr = rm[slot] - marg[slot];
                if (__any_sync(0xffffffffu, mx >= thr - 0.015f)) {
                    #pragma unroll
                    for (int eb = 0; eb < 8; eb++)
                        #pragma unroll
                        for (int j = 0; j < 2; j++) {
                            float vv = acc[qb][eb][h * 2 + j];
                            if (vv >= thr) {
                                int sc = atomicAdd(&scnt[rloc[slot]], 1);
                                if (sc < CAP)
                                    scand[rloc[slot] * CAP + sc] =
                                        t * NT + ew + eb * 8 + (l & 3) * 2 + j;
                            }
                        }
                }
            }
        __syncthreads();
    }

    // ======================= fused rescore tail =======================
    // reload fp32 z rows into the (now dead) B buffers: zsh[c*128+q]
    #pragma unroll
    for (int i = 0; i < 32; i++) {
        int idx = tid + i * 256;       // 8192 = 64c * 128q
        int c = idx >> 7, q2 = idx & 127;
        zsh[c * 128 + q2] = zb[(size_t)c * 1024 + q2];
    }
    __syncthreads();

    // warp w rescores rows w*16 .. w*16+15; TWO rows at a time, half-warp
    // per row (lanes 0-15 row A, 16-31 row B).  Exact fp32, first-index
    // tie-break via packed key: (fkey(v) << 32) | (0x7FFFFFFF - e).
    const float* embg = g_embn + (size_t)g * NEG * KD;
    const int hw16 = l >> 4;          // 0 or 1: which row of the pair
    const int lg   = l & 15;          // lane within half-warp
    for (int rp = 0; rp < 8; rp++) {
        const int rq  = w * 16 + rp * 2 + hw16;
        const int cnt = scnt[rq];
        ull best = ((ull)fkey(-3.0e38f) << 32);   // be = 0x7FFFFFFF -> low 0
        if (cnt > CAP) {
            for (int e = lg; e < NEG; e += 16) {
                const float4* er = reinterpret_cast<const float4*>(
                    embg + (size_t)e * KD);
                float acc = 0.0f;
                #pragma unroll
                for (int kk = 0; kk < 16; kk++) {
                    float4 ev = er[kk];
                    acc = fmaf(zsh[(kk * 4 + 0) * 128 + rq], ev.x, acc);
                    acc = fmaf(zsh[(kk * 4 + 1) * 128 + rq], ev.y, acc);
                    acc = fmaf(zsh[(kk * 4 + 2) * 128 + rq], ev.z, acc);
                    acc = fmaf(zsh[(kk * 4 + 3) * 128 + rq], ev.w, acc);
                }
                ull pk = ((ull)fkey(acc) << 32) | (unsigned)(0x7FFFFFFF - e);
                if (pk > best) best = pk;
            }
        } else {
            for (int cb = 0; cb < cnt; cb += 16) {
                int c = cb + lg;
                if (c < cnt) {
                    int e = scand[rq * CAP + c];
                    const float4* er = reinterpret_cast<const float4*>(
                        embg + (size_t)e * KD);
                    float acc = 0.0f;
                    #pragma unroll
                    for (int kk = 0; kk < 16; kk++) {
                        float4 ev = er[kk];
                        acc = fmaf(zsh[(kk * 4 + 0) * 128 + rq], ev.x, acc);
                        acc = fmaf(zsh[(kk * 4 + 1) * 128 + rq], ev.y, acc);
                        acc = fmaf(zsh[(kk * 4 + 2) * 128 + rq], ev.z, acc);
                        acc = fmaf(zsh[(kk * 4 + 3) * 128 + rq], ev.w, acc);
                    }
                    ull pk = ((ull)fkey(acc) << 32) | (unsigned)(0x7FFFFFFF - e);
                    if (pk > best) best = pk;
                }
            }
        }
        // 16-wide max reduction (both halves converged here)
        #pragma unroll
        for (int m = 8; m >= 1; m >>= 1) {
            ull o = __shfl_xor_sync(0xffffffffu, best, m, 16);
            if (o > best) best = o;
        }
        if (lg == 0) {
            int bi = 0x7FFFFFFF - (int)(unsigned)(best & 0xFFFFFFFFu);
            swin[rq] = bi;
            int n = qbase + rq;
            g_idx[n * GR + g] = bi;
            out[IDX_OFFC + (size_t)n * GR + g] = (float)bi;
        }
    }
    __syncthreads();

    // ======================= fused quant tail =======================
    // out[b, g*64+c, hwb+q] = embn[g*4096 + swin[q], c]; coalesced stores.
    {
        const int q  = tid & 127;
        const int ph = tid >> 7;                 // c = ph*32 .. +31
        const float* er = embg + (size_t)swin[q] * KD;
        float* oq = out + (size_t)b * 262144 + (size_t)(g * 64) * 1024 + hwb + q;
        #pragma unroll
        for (int i = 0; i < 32; i++) {
            int c = ph * 32 + i;
            oq[(size_t)c * 1024] = er[c];
        }
    }
}

// ============================================================================
// Scatter one-hot + histogram; the LAST block also reduces the histogram
// into perplexity (last-block pattern: threadfence + arrival counter).
// ============================================================================
__global__ void scatter_perp_kernel(float* __restrict__ out_me,
                                    float* __restrict__ out_p)
{
    __shared__ float red[32];
    __shared__ int   isLast;

    int tid = threadIdx.x;
    int n = blockIdx.x * blockDim.x + tid;
    if (n < NQ) {
        int v = g_idx[n * GR + 3];
        out_me[(size_t)n * NEG + v] = 1.0f;
        atomicAdd(&g_hist[v], 1);
    }

    __threadfence();
    __syncthreads();
    if (tid == 0) {
        int c = atomicAdd(&g_done, 1);
        isLast = (c == (int)gridDim.x - 1);
    }
    __syncthreads();

    if (isLast) {
        float s = 0.0f;
        for (int i = tid; i < NEG; i += blockDim.x) {
            float p = (float)g_hist[i] * (1.0f / 16384.0f);
            s += p * logf(p + 1e-10f);
        }
        #pragma unroll
        for (int m = 16; m >= 1; m >>= 1) s += __shfl_xor_sync(0xffffffffu, s, m);
        if ((tid & 31) == 0) red[tid >> 5] = s;
        __syncthreads();
        if (tid < 32) {
            float x = (tid < (int)(blockDim.x >> 5)) ? red[tid] : 0.0f;
            #pragma unroll
            for (int m = 16; m >= 1; m >>= 1)
                x += __shfl_xor_sync(0xffffffffu, x, m);
            if (tid == 0) out_p[0] = expf(-x);
        }
    }
}

// ============================================================================
// Output layout (fp32, concatenated, 71,368,717 elements):
//   [0, 4194304)            quant          (written in vq_fused_kernel)
//   [4194304, +12)          losses = zeros (written in embprep_kernel)
//   [4194316]               perplexity     (scatter_perp_kernel)
//   [4194317, +16384*4096)  min_encodings  (zeroed in vq_fused_kernel,
//                                           one-hot in scatter_perp_kernel)
//   [71303181, +65536)      idx            (written in vq_fused_kernel)
// ============================================================================
extern "C" void kernel_launch(void* const* d_in, const int* in_sizes, int n_in,
                              void* d_out, int out_size)
{
    const float* z   = (const float*)d_in[0];
    const float* emb = (const float*)d_in[1];
    float* out = (float*)d_out;

    const int SMEM = 83968;
    cudaFuncSetAttribute(vq_fused_kernel,
                         cudaFuncAttributeMaxDynamicSharedMemorySize, SMEM);

    embprep_kernel<<<2048, 256>>>(emb, out);

    vq_fused_kernel<<<512, 256, SMEM>>>(z, out);

    scatter_perp_kernel<<<64, 256>>>(out + ME_OFFC, out + QUANT_SZ + 12);
}